// round 5
// baseline (speedup 1.0000x reference)
#include <cuda_runtime.h>
#include <cuda_bf16.h>
#include <cstdint>

// Problem constants
#define MAX_NODES 100000
#define FEAT 64                      // floats per node feature row
#define FEAT4 16                     // float4s per node feature row

// Scratch: float4-typed so 16B-wide vector atomics are guaranteed aligned.
__device__ float4 g_accum4[(size_t)MAX_NODES * FEAT4];
__device__ float  g_deg[MAX_NODES];

// ---------------------------------------------------------------------------
// Kernel 0: zero scratch (grid-stride-free exact launch).
// ---------------------------------------------------------------------------
__global__ void zero_kernel(int n_accum4, int n_deg) {
    int t = blockIdx.x * blockDim.x + threadIdx.x;
    if (t < n_accum4) g_accum4[t] = make_float4(0.f, 0.f, 0.f, 0.f);
    if (t < n_deg)    g_deg[t] = 0.f;
}

// ---------------------------------------------------------------------------
// Kernel 1: edge scatter. 4 threads per edge; each thread handles 16 floats
// (4x float4) with vector atomics (sm_90+ atomicAdd(float4*)).
// Indices are INT32 (JAX default config downcasts int64 -> int32).
// ---------------------------------------------------------------------------
__global__ void scatter_kernel(const float4* __restrict__ h4,
                               const int* __restrict__ src,
                               const int* __restrict__ dst,
                               int total /* = 4*E */) {
    int t = blockIdx.x * blockDim.x + threadIdx.x;
    if (t >= total) return;
    int e = t >> 2;
    int c = t & 3;
    int s = src[e];
    int d = dst[e];
    const float4* hp = h4 + (size_t)s * FEAT4 + c * 4;
    float4* ap = g_accum4 + (size_t)d * FEAT4 + c * 4;
    float4 v0 = hp[0];
    float4 v1 = hp[1];
    float4 v2 = hp[2];
    float4 v3 = hp[3];
    atomicAdd(ap + 0, v0);
    atomicAdd(ap + 1, v1);
    atomicAdd(ap + 2, v2);
    atomicAdd(ap + 3, v3);
    if (c == 0) {
        atomicAdd(g_deg + d, 1.0f);
    }
}

// ---------------------------------------------------------------------------
// Kernel 2: fused combine + linear.
// Block = 256 threads handles 64 nodes x 64 outputs.
// Thread (ty = tid/16, tx = tid%16) computes a 4x4 micro-tile:
//   nodes  nb + ty*4 + i   (i = 0..3)
//   outs   tx*4 + j        (j = 0..3)
// x[n][k]: k<64 from h, k>=64 from accum/max(deg,1).
// Shared layouts:
//   sW: [64 outs][129]  (odd stride -> 2-way worst-case conflict on reads)
//   sX: [64 nodes][132] (float4-staged; compute reads are broadcasts)
// ---------------------------------------------------------------------------
#define SW_PAD 129
#define SX_PAD 132
#define GEMM_SMEM_FLOATS (64 * SW_PAD + 64 * SX_PAD)
#define GEMM_SMEM_BYTES (GEMM_SMEM_FLOATS * 4)

__global__ void fused_gemm_kernel(const float* __restrict__ h,
                                  const float* __restrict__ W,
                                  const float* __restrict__ b,
                                  float* __restrict__ out,
                                  int N) {
    extern __shared__ float smem[];
    float* sW = smem;                 // 64 * 129
    float* sX = smem + 64 * SW_PAD;   // 64 * 132

    const float* accum = (const float*)g_accum4;

    const int tid = threadIdx.x;
    const int nb = blockIdx.x * 64;

    // Stage W: 64 rows x 128 floats = 2048 float4 quads.
    // Lanes in a warp share o with consecutive kq: coalesced LDG.128;
    // scalar STS to consecutive floats (conflict-free).
    for (int q = tid; q < 2048; q += 256) {
        int o  = q >> 5;
        int kq = q & 31;
        float4 v = *(const float4*)(W + o * 128 + kq * 4);
        float* p = sW + o * SW_PAD + kq * 4;
        p[0] = v.x; p[1] = v.y; p[2] = v.z; p[3] = v.w;
    }

    // Stage X: 64 nodes x 128 floats (first 64 = h, next 64 = accum/deg).
    for (int q = tid; q < 2048; q += 256) {
        int n  = q >> 5;
        int kq = q & 31;
        int gn = nb + n;
        float4 v = make_float4(0.f, 0.f, 0.f, 0.f);
        if (gn < N) {
            if (kq < 16) {
                v = *(const float4*)(h + (size_t)gn * 64 + kq * 4);
            } else {
                v = *(const float4*)(accum + (size_t)gn * 64 + (kq - 16) * 4);
                float inv = 1.0f / fmaxf(g_deg[gn], 1.0f);
                v.x *= inv; v.y *= inv; v.z *= inv; v.w *= inv;
            }
        }
        *(float4*)(sX + n * SX_PAD + kq * 4) = v;
    }
    __syncthreads();

    const int tx = tid & 15;
    const int ty = tid >> 4;

    float acc[4][4];
    {
        float b0 = b[tx * 4 + 0];
        float b1 = b[tx * 4 + 1];
        float b2 = b[tx * 4 + 2];
        float b3 = b[tx * 4 + 3];
#pragma unroll
        for (int i = 0; i < 4; i++) {
            acc[i][0] = b0; acc[i][1] = b1; acc[i][2] = b2; acc[i][3] = b3;
        }
    }

#pragma unroll 4
    for (int k = 0; k < 128; k++) {
        float xv[4], wv[4];
#pragma unroll
        for (int i = 0; i < 4; i++) xv[i] = sX[(ty * 4 + i) * SX_PAD + k];
#pragma unroll
        for (int j = 0; j < 4; j++) wv[j] = sW[(tx * 4 + j) * SW_PAD + k];
#pragma unroll
        for (int i = 0; i < 4; i++)
#pragma unroll
            for (int j = 0; j < 4; j++)
                acc[i][j] = fmaf(xv[i], wv[j], acc[i][j]);
    }

#pragma unroll
    for (int i = 0; i < 4; i++) {
        int gn = nb + ty * 4 + i;
        if (gn < N) {
            *(float4*)(out + (size_t)gn * 64 + tx * 4) =
                make_float4(acc[i][0], acc[i][1], acc[i][2], acc[i][3]);
        }
    }
}

// ---------------------------------------------------------------------------
// Launch
// ---------------------------------------------------------------------------
extern "C" void kernel_launch(void* const* d_in, const int* in_sizes, int n_in,
                              void* d_out, int out_size) {
    const float* h   = (const float*)d_in[0];
    const int*   src = (const int*)d_in[1];   // int32 indices (JAX default)
    const int*   dst = (const int*)d_in[2];
    const float* W   = (const float*)d_in[3];
    const float* b   = (const float*)d_in[4];
    float*       out = (float*)d_out;

    const int N = in_sizes[0] / FEAT;   // 100000
    const int E = in_sizes[1];          // 1600000

    // Zero scratch
    {
        int n_accum4 = N * FEAT4;       // 1.6M float4
        int blocks = (n_accum4 + 255) / 256;
        zero_kernel<<<blocks, 256>>>(n_accum4, N);
    }

    // Edge scatter
    {
        int total = 4 * E;
        int blocks = (total + 255) / 256;
        scatter_kernel<<<blocks, 256>>>((const float4*)h, src, dst, total);
    }

    // Fused combine + GEMM
    {
        cudaFuncSetAttribute(fused_gemm_kernel,
                             cudaFuncAttributeMaxDynamicSharedMemorySize,
                             GEMM_SMEM_BYTES);
        int blocks = (N + 63) / 64;
        fused_gemm_kernel<<<blocks, 256, GEMM_SMEM_BYTES>>>(h, W, b, out, N);
    }
}

// round 6
// speedup vs baseline: 1.3761x; 1.3761x over previous
#include <cuda_runtime.h>
#include <cuda_bf16.h>
#include <cstdint>

#define MAX_NODES 100000
#define MAX_EDGES 1600000
#define FEAT 64
#define FEAT4 16
#define SCAN_CHUNK 256
#define MAX_SCAN_BLOCKS ((MAX_NODES + SCAN_CHUNK - 1) / SCAN_CHUNK)   // 391

// Scratch (device globals; no allocation allowed)
__device__ float4 g_accum4[(size_t)MAX_NODES * FEAT4];
__device__ int    g_count[MAX_NODES];
__device__ int    g_off[MAX_NODES + 1];
__device__ int    g_cursor[MAX_NODES];
__device__ int    g_sorted[MAX_EDGES];
__device__ int    g_bsums[MAX_SCAN_BLOCKS];

// ---------------------------------------------------------------------------
// K0: zero degree counters (only 0.4MB — the 25.6MB accum zero is gone).
// ---------------------------------------------------------------------------
__global__ void zero_count_kernel(int N) {
    int t = blockIdx.x * blockDim.x + threadIdx.x;
    if (t < N) g_count[t] = 0;
}

// ---------------------------------------------------------------------------
// K1: histogram of dst (degree counts).
// ---------------------------------------------------------------------------
__global__ void hist_kernel(const int* __restrict__ dst, int E) {
    int e = blockIdx.x * blockDim.x + threadIdx.x;
    if (e < E) atomicAdd(&g_count[dst[e]], 1);
}

// ---------------------------------------------------------------------------
// K2a: per-block reduction of counts -> block sums.
// ---------------------------------------------------------------------------
__global__ void scanA_kernel(int N) {
    __shared__ int warp_sums[8];
    int i = blockIdx.x * SCAN_CHUNK + threadIdx.x;
    int v = (i < N) ? g_count[i] : 0;
    // warp reduce
    for (int o = 16; o > 0; o >>= 1) v += __shfl_down_sync(0xffffffffu, v, o);
    if ((threadIdx.x & 31) == 0) warp_sums[threadIdx.x >> 5] = v;
    __syncthreads();
    if (threadIdx.x < 8) {
        int s = warp_sums[threadIdx.x];
        for (int o = 4; o > 0; o >>= 1) s += __shfl_down_sync(0xffu, s, o);
        if (threadIdx.x == 0) g_bsums[blockIdx.x] = s;
    }
}

// ---------------------------------------------------------------------------
// K2b: exclusive scan of block sums (single block, NB <= 512).
// ---------------------------------------------------------------------------
__global__ void scanB_kernel(int NB) {
    __shared__ int s[512];
    int t = threadIdx.x;
    int v = (t < NB) ? g_bsums[t] : 0;
    s[t] = v;
    __syncthreads();
    for (int o = 1; o < 512; o <<= 1) {
        int x = (t >= o) ? s[t - o] : 0;
        __syncthreads();
        s[t] += x;
        __syncthreads();
    }
    if (t < NB) g_bsums[t] = s[t] - v;   // exclusive
}

// ---------------------------------------------------------------------------
// K2c: local exclusive scan + block base -> offsets and cursor copy.
// ---------------------------------------------------------------------------
__global__ void scanC_kernel(int N) {
    __shared__ int s[SCAN_CHUNK];
    int t = threadIdx.x;
    int i = blockIdx.x * SCAN_CHUNK + t;
    int v = (i < N) ? g_count[i] : 0;
    s[t] = v;
    __syncthreads();
    for (int o = 1; o < SCAN_CHUNK; o <<= 1) {
        int x = (t >= o) ? s[t - o] : 0;
        __syncthreads();
        s[t] += x;
        __syncthreads();
    }
    int incl = s[t];
    int base = g_bsums[blockIdx.x];
    if (i < N) {
        int off = base + incl - v;
        g_off[i] = off;
        g_cursor[i] = off;
        if (i == N - 1) g_off[N] = base + incl;
    }
}

// ---------------------------------------------------------------------------
// K3: reorder src into dst-sorted order.
// ---------------------------------------------------------------------------
__global__ void reorder_kernel(const int* __restrict__ src,
                               const int* __restrict__ dst, int E) {
    int e = blockIdx.x * blockDim.x + threadIdx.x;
    if (e < E) {
        int d = dst[e];
        int p = atomicAdd(&g_cursor[d], 1);
        g_sorted[p] = src[e];
    }
}

// ---------------------------------------------------------------------------
// K4: atomic-free segmented gather-sum. 16 lanes per node; each lane owns one
// float4 of the 64-float row. 2-way unrolled edge loop for MLP.
// ---------------------------------------------------------------------------
__global__ void gather_kernel(const float4* __restrict__ h4, int N) {
    int idx = blockIdx.x * blockDim.x + threadIdx.x;
    int node = idx >> 4;
    int lane = idx & 15;
    if (node >= N) return;
    int beg = g_off[node];
    int end = g_off[node + 1];
    float4 acc = make_float4(0.f, 0.f, 0.f, 0.f);
    int j = beg;
    for (; j + 1 < end; j += 2) {
        int s0 = g_sorted[j];
        int s1 = g_sorted[j + 1];
        float4 v0 = __ldg(h4 + (size_t)s0 * FEAT4 + lane);
        float4 v1 = __ldg(h4 + (size_t)s1 * FEAT4 + lane);
        acc.x += v0.x; acc.y += v0.y; acc.z += v0.z; acc.w += v0.w;
        acc.x += v1.x; acc.y += v1.y; acc.z += v1.z; acc.w += v1.w;
    }
    if (j < end) {
        int s0 = g_sorted[j];
        float4 v0 = __ldg(h4 + (size_t)s0 * FEAT4 + lane);
        acc.x += v0.x; acc.y += v0.y; acc.z += v0.z; acc.w += v0.w;
    }
    g_accum4[(size_t)node * FEAT4 + lane] = acc;   // raw sum; divide in GEMM
}

// ---------------------------------------------------------------------------
// K5: fused combine + linear (unchanged structure).
// Block = 256 threads -> 64 nodes x 64 outputs, 4x4 micro-tile per thread.
// ---------------------------------------------------------------------------
#define SW_PAD 129
#define SX_PAD 132
#define GEMM_SMEM_FLOATS (64 * SW_PAD + 64 * SX_PAD)
#define GEMM_SMEM_BYTES (GEMM_SMEM_FLOATS * 4)

__global__ void fused_gemm_kernel(const float* __restrict__ h,
                                  const float* __restrict__ W,
                                  const float* __restrict__ b,
                                  float* __restrict__ out,
                                  int N) {
    extern __shared__ float smem[];
    float* sW = smem;                 // 64 * 129
    float* sX = smem + 64 * SW_PAD;   // 64 * 132

    const float* accum = (const float*)g_accum4;

    const int tid = threadIdx.x;
    const int nb = blockIdx.x * 64;

    // Stage W: 64 rows x 128 floats = 2048 float4 quads.
    for (int q = tid; q < 2048; q += 256) {
        int o  = q >> 5;
        int kq = q & 31;
        float4 v = *(const float4*)(W + o * 128 + kq * 4);
        float* p = sW + o * SW_PAD + kq * 4;
        p[0] = v.x; p[1] = v.y; p[2] = v.z; p[3] = v.w;
    }

    // Stage X: 64 nodes x 128 floats (first 64 = h, next 64 = accum/deg).
    for (int q = tid; q < 2048; q += 256) {
        int n  = q >> 5;
        int kq = q & 31;
        int gn = nb + n;
        float4 v = make_float4(0.f, 0.f, 0.f, 0.f);
        if (gn < N) {
            if (kq < 16) {
                v = *(const float4*)(h + (size_t)gn * 64 + kq * 4);
            } else {
                v = *(const float4*)(accum + (size_t)gn * 64 + (kq - 16) * 4);
                float inv = 1.0f / fmaxf((float)g_count[gn], 1.0f);
                v.x *= inv; v.y *= inv; v.z *= inv; v.w *= inv;
            }
        }
        *(float4*)(sX + n * SX_PAD + kq * 4) = v;
    }
    __syncthreads();

    const int tx = tid & 15;
    const int ty = tid >> 4;

    float acc[4][4];
    {
        float b0 = b[tx * 4 + 0];
        float b1 = b[tx * 4 + 1];
        float b2 = b[tx * 4 + 2];
        float b3 = b[tx * 4 + 3];
#pragma unroll
        for (int i = 0; i < 4; i++) {
            acc[i][0] = b0; acc[i][1] = b1; acc[i][2] = b2; acc[i][3] = b3;
        }
    }

#pragma unroll 4
    for (int k = 0; k < 128; k++) {
        float xv[4], wv[4];
#pragma unroll
        for (int i = 0; i < 4; i++) xv[i] = sX[(ty * 4 + i) * SX_PAD + k];
#pragma unroll
        for (int j = 0; j < 4; j++) wv[j] = sW[(tx * 4 + j) * SW_PAD + k];
#pragma unroll
        for (int i = 0; i < 4; i++)
#pragma unroll
            for (int j = 0; j < 4; j++)
                acc[i][j] = fmaf(xv[i], wv[j], acc[i][j]);
    }

#pragma unroll
    for (int i = 0; i < 4; i++) {
        int gn = nb + ty * 4 + i;
        if (gn < N) {
            *(float4*)(out + (size_t)gn * 64 + tx * 4) =
                make_float4(acc[i][0], acc[i][1], acc[i][2], acc[i][3]);
        }
    }
}

// ---------------------------------------------------------------------------
// Launch
// ---------------------------------------------------------------------------
extern "C" void kernel_launch(void* const* d_in, const int* in_sizes, int n_in,
                              void* d_out, int out_size) {
    const float* h   = (const float*)d_in[0];
    const int*   src = (const int*)d_in[1];   // int32 indices
    const int*   dst = (const int*)d_in[2];
    const float* W   = (const float*)d_in[3];
    const float* b   = (const float*)d_in[4];
    float*       out = (float*)d_out;

    const int N = in_sizes[0] / FEAT;   // 100000
    const int E = in_sizes[1];          // 1600000
    const int NB = (N + SCAN_CHUNK - 1) / SCAN_CHUNK;   // 391

    zero_count_kernel<<<(N + 255) / 256, 256>>>(N);
    hist_kernel<<<(E + 255) / 256, 256>>>(dst, E);
    scanA_kernel<<<NB, SCAN_CHUNK>>>(N);
    scanB_kernel<<<1, 512>>>(NB);
    scanC_kernel<<<NB, SCAN_CHUNK>>>(N);
    reorder_kernel<<<(E + 255) / 256, 256>>>(src, dst, E);
    gather_kernel<<<(N * 16 + 255) / 256, 256>>>((const float4*)h, N);

    cudaFuncSetAttribute(fused_gemm_kernel,
                         cudaFuncAttributeMaxDynamicSharedMemorySize,
                         GEMM_SMEM_BYTES);
    fused_gemm_kernel<<<(N + 63) / 64, 256, GEMM_SMEM_BYTES>>>(h, W, b, out, N);
}